// round 9
// baseline (speedup 1.0000x reference)
#include <cuda_runtime.h>
#include <math.h>
#include <stdint.h>

#define B_ 4
#define S_ 2048
#define DM 512
#define H_ 8

// Scratch (device globals — no runtime allocation allowed)
__device__ float g_buf[(size_t)B_*S_*DM];
__device__ float g_qp [(size_t)B_*S_*DM];
__device__ float g_kp [(size_t)B_*S_*DM];
__device__ float g_vp [(size_t)B_*S_*DM];
__device__ float g_oh [(size_t)B_*S_*DM];

// ---------------- tf32 helpers ----------------
__device__ __forceinline__ float tf32r(float x) {
    uint32_t u;
    asm("cvt.rna.tf32.f32 %0, %1;" : "=r"(u) : "f"(x));
    return __uint_as_float(u);
}
// D += A(16x8 tf32) * B(8x8 tf32); acc fp32. Baseline PTX (sm_80+), legacy HMMA pipe.
__device__ __forceinline__ void mma8(float* c, float4 a, float b0, float b1) {
    asm("mma.sync.aligned.m16n8k8.row.col.f32.tf32.tf32.f32 "
        "{%0,%1,%2,%3}, {%4,%5,%6,%7}, {%8,%9}, {%0,%1,%2,%3};"
        : "+f"(c[0]), "+f"(c[1]), "+f"(c[2]), "+f"(c[3])
        : "r"(__float_as_uint(a.x)), "r"(__float_as_uint(a.y)),
          "r"(__float_as_uint(a.z)), "r"(__float_as_uint(a.w)),
          "r"(__float_as_uint(b0)), "r"(__float_as_uint(b1)));
}

// =====================================================================
// Shared tf32x3 GEMM core.  C[128, 64] = A[128, K] * B^T  (B as [n][k],
// or V[k][n] when btrans).  8 warps = 4(m) x 2(n); warp tile 32x32.
// Each K-chunk of 32 is staged to smem in *fragment order* (hi & lo tf32
// split), so the hot loop is LDS.128 + HMMA only.
// smem floats: A_hi[4096] A_lo[4096] B_hi[2048] B_lo[2048] = 48KB.
// Fragment layouts (m16n8k8, lane l: g=l>>2, t=l&3):
//   A tile (mt,kc): [((kc*8+mt)*32+lane)*4 + r], r = (row>>3&1) | ((col>>2&1)<<1)
//   B pair (p,kc):  [((kc*4+p)*32+lane)*4 + sub*2 + r], sub = nt&1, r = k>>2&1
// =====================================================================
__device__ __forceinline__ void gemm_core(
    const float* __restrict__ Ab, size_t lda,
    const float* __restrict__ Bb, size_t ldb,
    float* __restrict__ Cb, size_t ldc,
    float scale, int nchunk, bool btrans, float* sm)
{
    float* sAh = sm;
    float* sAl = sm + 4096;
    float* sBh = sm + 8192;
    float* sBl = sm + 10240;
    int tid = threadIdx.x, lane = tid & 31, wid = tid >> 5;
    int wm = wid & 3, wn = wid >> 2;
    int g = lane >> 2, t = lane & 3;

    float acc[2][4][4] = {};

    for (int c = 0; c < nchunk; c++) {
        // ---- stage A chunk: 128 rows x 32 cols ----
        {
            const float* As = Ab + c * 32;
            #pragma unroll
            for (int i = 0; i < 4; i++) {
                int lin = tid + i * 256;
                int m = lin >> 3, k4 = (lin & 7) << 2;
                float4 f = *(const float4*)&As[(size_t)m * lda + k4];
                int base = (((k4 >> 3) * 8 + (m >> 4)) * 32 + (m & 7) * 4) * 4
                         + ((m >> 3) & 1) + ((k4 >> 2) & 1) * 2;
                float xs[4] = {f.x, f.y, f.z, f.w};
                #pragma unroll
                for (int j = 0; j < 4; j++) {
                    float h = tf32r(xs[j]);
                    sAh[base + j * 4] = h;
                    sAl[base + j * 4] = tf32r(xs[j] - h);
                }
            }
        }
        // ---- stage B chunk: 64 n x 32 k ----
        if (!btrans) {
            const float* Bs = Bb + c * 32;
            #pragma unroll
            for (int i = 0; i < 2; i++) {
                int lin = tid + i * 256;
                int n = lin >> 3, k4 = (lin & 7) << 2;
                float4 f = *(const float4*)&Bs[(size_t)n * ldb + k4];
                int base = (((k4 >> 3) * 4 + (n >> 4)) * 32 + (n & 7) * 4) * 4
                         + ((n >> 3) & 1) * 2 + ((k4 >> 2) & 1);
                float xs[4] = {f.x, f.y, f.z, f.w};
                #pragma unroll
                for (int j = 0; j < 4; j++) {     // j advances k -> lane t
                    float h = tf32r(xs[j]);
                    sBh[base + j * 4] = h;
                    sBl[base + j * 4] = tf32r(xs[j] - h);
                }
            }
        } else {
            const float* Bs = Bb + (size_t)(c * 32) * ldb;   // V rows = k
            #pragma unroll
            for (int i = 0; i < 2; i++) {
                int lin = tid + i * 256;
                int k = lin >> 4, dv4 = (lin & 15) << 2;
                float4 f = *(const float4*)&Bs[(size_t)k * ldb + dv4];
                int base = (((k >> 3) * 4 + (dv4 >> 4)) * 32 + (dv4 & 7) * 4 + (k & 3)) * 4
                         + ((dv4 >> 3) & 1) * 2 + ((k >> 2) & 1);
                float xs[4] = {f.x, f.y, f.z, f.w};
                #pragma unroll
                for (int j = 0; j < 4; j++) {     // j advances n -> +16 floats
                    float h = tf32r(xs[j]);
                    sBh[base + j * 16] = h;
                    sBl[base + j * 16] = tf32r(xs[j] - h);
                }
            }
        }
        __syncthreads();

        // ---- compute: 4 k8-steps ----
        #pragma unroll
        for (int kc = 0; kc < 4; kc++) {
            float4 Ah[2], Al[2], Bh2[2], Bl2[2];
            #pragma unroll
            for (int mt = 0; mt < 2; mt++) {
                int off = ((kc * 8 + wm * 2 + mt) * 32 + lane) * 4;
                Ah[mt] = *(const float4*)&sAh[off];
                Al[mt] = *(const float4*)&sAl[off];
            }
            #pragma unroll
            for (int p = 0; p < 2; p++) {
                int off = ((kc * 4 + wn * 2 + p) * 32 + lane) * 4;
                Bh2[p] = *(const float4*)&sBh[off];
                Bl2[p] = *(const float4*)&sBl[off];
            }
            #pragma unroll
            for (int mt = 0; mt < 2; mt++) {
                #pragma unroll
                for (int p = 0; p < 2; p++) {
                    mma8(acc[mt][p * 2 + 0], Ah[mt], Bh2[p].x, Bh2[p].y);
                    mma8(acc[mt][p * 2 + 0], Ah[mt], Bl2[p].x, Bl2[p].y);
                    mma8(acc[mt][p * 2 + 0], Al[mt], Bh2[p].x, Bh2[p].y);
                    mma8(acc[mt][p * 2 + 1], Ah[mt], Bh2[p].z, Bh2[p].w);
                    mma8(acc[mt][p * 2 + 1], Ah[mt], Bl2[p].z, Bl2[p].w);
                    mma8(acc[mt][p * 2 + 1], Al[mt], Bh2[p].z, Bh2[p].w);
                }
            }
        }
        __syncthreads();
    }

    // ---- epilogue: warp tile 32x32 at (wm*32, wn*32) ----
    #pragma unroll
    for (int mt = 0; mt < 2; mt++) {
        #pragma unroll
        for (int nt = 0; nt < 4; nt++) {
            size_t row = (size_t)(wm * 32 + mt * 16 + g);
            size_t col = (size_t)(wn * 32 + nt * 8 + t * 2);
            float2 v0 = {acc[mt][nt][0] * scale, acc[mt][nt][1] * scale};
            float2 v1 = {acc[mt][nt][2] * scale, acc[mt][nt][3] * scale};
            *(float2*)&Cb[row * ldc + col] = v0;
            *(float2*)&Cb[(row + 8) * ldc + col] = v1;
        }
    }
}

// ---------------- kernels ----------------
__global__ __launch_bounds__(256) void proj_mma(const float* __restrict__ A,
                                                const float* __restrict__ W,
                                                float* __restrict__ C) {
    extern __shared__ float sm[];
    gemm_core(A + (size_t)blockIdx.y * 128 * DM, DM,
              W + (size_t)blockIdx.x * 64 * DM, DM,
              C + (size_t)blockIdx.y * 128 * DM + blockIdx.x * 64, DM,
              1.0f, DM / 32, false, sm);
}

__global__ __launch_bounds__(256) void scores_mma(const float* __restrict__ qp,
                                                  const float* __restrict__ kp,
                                                  float* __restrict__ attn) {
    extern __shared__ float sm[];
    int bh = blockIdx.z, b = bh >> 3, h = bh & 7;
    size_t sq0 = (size_t)blockIdx.y * 128, sk0 = (size_t)blockIdx.x * 64;
    gemm_core(qp + ((size_t)b * S_ + sq0) * DM + h * 64, DM,
              kp + ((size_t)b * S_ + sk0) * DM + h * 64, DM,
              attn + ((size_t)bh * S_ + sq0) * S_ + sk0, S_,
              0.125f, 2, false, sm);
}

__global__ __launch_bounds__(256) void av_mma(const float* __restrict__ attn,
                                              const float* __restrict__ vp,
                                              float* __restrict__ oh) {
    extern __shared__ float sm[];
    int bh = blockIdx.y, b = bh >> 3, h = bh & 7;
    size_t sq0 = (size_t)blockIdx.x * 128;
    gemm_core(attn + ((size_t)bh * S_ + sq0) * S_, S_,
              vp + (size_t)b * S_ * DM + h * 64, DM,
              oh + ((size_t)b * S_ + sq0) * DM + h * 64, DM,
              1.0f, S_ / 32, true, sm);
}

// ---------------- LayerNorm ----------------
__global__ void ln_kernel(const float* __restrict__ x, float* __restrict__ y,
                          const float* __restrict__ g, const float* __restrict__ bb) {
    int row = blockIdx.x;
    int tid = threadIdx.x;
    const float* xr = x + (size_t)row * DM;
    float v0 = xr[tid], v1 = xr[tid + 256];
    __shared__ float red[256];
    red[tid] = v0 + v1;
    __syncthreads();
    for (int o = 128; o > 0; o >>= 1) { if (tid < o) red[tid] += red[tid + o]; __syncthreads(); }
    float mu = red[0] * (1.0f / DM);
    __syncthreads();
    float d0 = v0 - mu, d1 = v1 - mu;
    red[tid] = d0 * d0 + d1 * d1;
    __syncthreads();
    for (int o = 128; o > 0; o >>= 1) { if (tid < o) red[tid] += red[tid + o]; __syncthreads(); }
    float rstd = rsqrtf(red[0] * (1.0f / DM) + 1e-5f);
    float* yr = y + (size_t)row * DM;
    yr[tid]       = d0 * rstd * g[tid]       + bb[tid];
    yr[tid + 256] = d1 * rstd * g[tid + 256] + bb[tid + 256];
}

// ---------------- softmax in place over rows of 2048 (float4) ----------------
__global__ __launch_bounds__(256) void softmax_kernel(float* __restrict__ attn) {
    size_t row = blockIdx.x;
    float4* p = (float4*)(attn + row * (size_t)S_);
    int tid = threadIdx.x;
    float4 v0 = p[tid], v1 = p[tid + 256];
    float m = fmaxf(fmaxf(fmaxf(v0.x, v0.y), fmaxf(v0.z, v0.w)),
                    fmaxf(fmaxf(v1.x, v1.y), fmaxf(v1.z, v1.w)));
    __shared__ float red[256];
    red[tid] = m;
    __syncthreads();
    for (int o = 128; o > 0; o >>= 1) { if (tid < o) red[tid] = fmaxf(red[tid], red[tid + o]); __syncthreads(); }
    m = red[0];
    __syncthreads();
    v0.x = __expf(v0.x - m); v0.y = __expf(v0.y - m); v0.z = __expf(v0.z - m); v0.w = __expf(v0.w - m);
    v1.x = __expf(v1.x - m); v1.y = __expf(v1.y - m); v1.z = __expf(v1.z - m); v1.w = __expf(v1.w - m);
    float s = v0.x + v0.y + v0.z + v0.w + v1.x + v1.y + v1.z + v1.w;
    red[tid] = s;
    __syncthreads();
    for (int o = 128; o > 0; o >>= 1) { if (tid < o) red[tid] += red[tid + o]; __syncthreads(); }
    float inv = 1.0f / red[0];
    v0.x *= inv; v0.y *= inv; v0.z *= inv; v0.w *= inv;
    v1.x *= inv; v1.y *= inv; v1.z *= inv; v1.w *= inv;
    p[tid] = v0;
    p[tid + 256] = v1;
}

extern "C" void kernel_launch(void* const* d_in, const int* in_sizes, int n_in,
                              void* d_out, int out_size) {
    const float* q    = (const float*)d_in[0];
    const float* k    = (const float*)d_in[1];
    const float* v    = (const float*)d_in[2];
    const float* W_Q  = (const float*)d_in[3];
    const float* W_K  = (const float*)d_in[4];
    const float* W_V  = (const float*)d_in[5];
    const float* W_fc = (const float*)d_in[6];
    const float* ln_g = (const float*)d_in[7];
    const float* ln_b = (const float*)d_in[8];

    float* out  = (float*)d_out;                       // [B,S,512]
    float* attn = out + (size_t)B_ * S_ * DM;          // [B,H,S,S]

    float *buf, *qp, *kp, *vp, *oh;
    cudaGetSymbolAddress((void**)&buf, g_buf);
    cudaGetSymbolAddress((void**)&qp,  g_qp);
    cudaGetSymbolAddress((void**)&kp,  g_kp);
    cudaGetSymbolAddress((void**)&vp,  g_vp);
    cudaGetSymbolAddress((void**)&oh,  g_oh);

    const int SMEM = 48 * 1024;
    cudaFuncSetAttribute(proj_mma,   cudaFuncAttributeMaxDynamicSharedMemorySize, SMEM);
    cudaFuncSetAttribute(scores_mma, cudaFuncAttributeMaxDynamicSharedMemorySize, SMEM);
    cudaFuncSetAttribute(av_mma,     cudaFuncAttributeMaxDynamicSharedMemorySize, SMEM);

    const int ROWS = B_ * S_;                          // 8192
    dim3 proj_grid(DM / 64, ROWS / 128);               // (8, 64)

    // Q path
    ln_kernel<<<ROWS, 256>>>(q, buf, ln_g, ln_b);
    proj_mma<<<proj_grid, 256, SMEM>>>(buf, W_Q, qp);
    // K path
    ln_kernel<<<ROWS, 256>>>(k, buf, ln_g, ln_b);
    proj_mma<<<proj_grid, 256, SMEM>>>(buf, W_K, kp);
    // V path
    ln_kernel<<<ROWS, 256>>>(v, buf, ln_g, ln_b);
    proj_mma<<<proj_grid, 256, SMEM>>>(buf, W_V, vp);

    // Attention
    scores_mma<<<dim3(S_ / 64, S_ / 128, B_ * H_), 256, SMEM>>>(qp, kp, attn);
    softmax_kernel<<<B_ * H_ * S_, 256>>>(attn);
    av_mma<<<dim3(S_ / 128, B_ * H_), 256, SMEM>>>(attn, vp, oh);

    // Output LN + fc
    ln_kernel<<<ROWS, 256>>>(oh, buf, ln_g, ln_b);
    proj_mma<<<proj_grid, 256, SMEM>>>(buf, W_fc, out);
}

// round 10
// speedup vs baseline: 2.0557x; 2.0557x over previous
#include <cuda_runtime.h>
#include <math.h>
#include <stdint.h>

#define B_ 4
#define S_ 2048
#define DM 512
#define H_ 8

// Scratch (device globals — no runtime allocation allowed)
__device__ float g_buf[(size_t)B_*S_*DM];
__device__ float g_qp [(size_t)B_*S_*DM];
__device__ float g_kp [(size_t)B_*S_*DM];
__device__ float g_vp [(size_t)B_*S_*DM];
__device__ float g_oh [(size_t)B_*S_*DM];

// ---------------- bf16 helpers ----------------
// pack {bf16(even) in low half, bf16(odd) in high half}
__device__ __forceinline__ uint32_t pack_bf16(float even, float odd) {
    uint32_t r;
    asm("cvt.rn.bf16x2.f32 %0, %1, %2;" : "=r"(r) : "f"(odd), "f"(even));
    return r;
}
// hi/lo split of two floats -> packed hi pair + packed lo pair
__device__ __forceinline__ void split2(float x0, float x1, uint32_t& hp, uint32_t& lp) {
    hp = pack_bf16(x0, x1);
    float h0 = __uint_as_float(hp << 16);            // bf16 -> f32 exact
    float h1 = __uint_as_float(hp & 0xFFFF0000u);
    lp = pack_bf16(x0 - h0, x1 - h1);
}
// D(16x8) += A(16x16 bf16) * B(16x8 bf16), fp32 acc. Baseline PTX (sm_80+).
__device__ __forceinline__ void mma16(float* c, uint4 a, uint32_t b0, uint32_t b1) {
    asm("mma.sync.aligned.m16n8k16.row.col.f32.bf16.bf16.f32 "
        "{%0,%1,%2,%3}, {%4,%5,%6,%7}, {%8,%9}, {%0,%1,%2,%3};"
        : "+f"(c[0]), "+f"(c[1]), "+f"(c[2]), "+f"(c[3])
        : "r"(a.x), "r"(a.y), "r"(a.z), "r"(a.w), "r"(b0), "r"(b1));
}

// =====================================================================
// bf16x3 GEMM core.  C[128, 64] = A[128, K] * B^T  (B as [n][k] row-major,
// or V[k][n] when BTRANS).  8 warps = 4(m) x 2(n); warp tile 32x32.
// K chunks of 32 (2 x k16), fragment-order smem, double-buffered.
// Buffer (b32 units): Ah[2048] Al[2048] Bh[1024] Bl[1024] = 24KB; x2 = 48KB.
// Fragment addressing (m16n8k16; lane = g*4+t, g=lane>>2, t=lane&3):
//  A elem (m,k): idx = ((kc*8 + m>>4)*32 + (m&7)*4 + ((k&15)>>1&3))*4
//                      + ((m>>3)&1) + 2*((k&15)>>3)      [pair packed on k&1]
//  B elem (n,k): idx = ((kc*4 + n>>4)*32 + (n&7)*4 + ((k&15)>>1&3))*4
//                      + ((n>>3)&1)*2 + ((k&15)>>3)      [pair packed on k&1]
// =====================================================================

__device__ __forceinline__ void loadA4(const float* __restrict__ As, size_t lda,
                                       int tid, float4* fa) {
    #pragma unroll
    for (int i = 0; i < 4; i++) {
        int lin = tid + i * 256;
        fa[i] = *(const float4*)&As[(size_t)(lin >> 3) * lda + ((lin & 7) << 2)];
    }
}
__device__ __forceinline__ void storeA4(const float4* fa, int tid,
                                        uint32_t* sAh, uint32_t* sAl) {
    #pragma unroll
    for (int i = 0; i < 4; i++) {
        int lin = tid + i * 256;
        int m = lin >> 3, k4 = (lin & 7) << 2;
        int kc = k4 >> 4, mt = m >> 4, halfm = (m >> 3) & 1, g4 = (m & 7) * 4;
        #pragma unroll
        for (int j = 0; j < 2; j++) {
            int lk = (k4 & 15) + 2 * j;
            int idx = ((kc * 8 + mt) * 32 + g4 + ((lk >> 1) & 3)) * 4
                    + halfm + 2 * ((lk >> 3) & 1);
            uint32_t hp, lp;
            if (j == 0) split2(fa[i].x, fa[i].y, hp, lp);
            else        split2(fa[i].z, fa[i].w, hp, lp);
            sAh[idx] = hp;
            sAl[idx] = lp;
        }
    }
}
__device__ __forceinline__ void loadB2(const float* __restrict__ Bs, size_t ldb,
                                       int tid, float4* fb) {
    #pragma unroll
    for (int i = 0; i < 2; i++) {
        int lin = tid + i * 256;
        fb[i] = *(const float4*)&Bs[(size_t)(lin >> 3) * ldb + ((lin & 7) << 2)];
    }
}
__device__ __forceinline__ void storeB2(const float4* fb, int tid,
                                        uint32_t* sBh, uint32_t* sBl) {
    #pragma unroll
    for (int i = 0; i < 2; i++) {
        int lin = tid + i * 256;
        int n = lin >> 3, k4 = (lin & 7) << 2;
        int kc = k4 >> 4, nt = n >> 4, haln = (n >> 3) & 1, g4 = (n & 7) * 4;
        #pragma unroll
        for (int j = 0; j < 2; j++) {
            int lk = (k4 & 15) + 2 * j;
            int idx = ((kc * 4 + nt) * 32 + g4 + ((lk >> 1) & 3)) * 4
                    + haln * 2 + ((lk >> 3) & 1);
            uint32_t hp, lp;
            if (j == 0) split2(fb[i].x, fb[i].y, hp, lp);
            else        split2(fb[i].z, fb[i].w, hp, lp);
            sBh[idx] = hp;
            sBl[idx] = lp;
        }
    }
}
// V[k][n] transposed staging: thread handles k rows (2*(tid>>4), +1), cols (tid&15)*4..+3
__device__ __forceinline__ void loadBT(const float* __restrict__ Bs, size_t ldb,
                                       int tid, float4* fb) {
    int k0 = (tid >> 4) * 2, dv4 = (tid & 15) << 2;
    fb[0] = *(const float4*)&Bs[(size_t)k0 * ldb + dv4];
    fb[1] = *(const float4*)&Bs[(size_t)(k0 + 1) * ldb + dv4];
}
__device__ __forceinline__ void storeBT(const float4* fb, int tid,
                                        uint32_t* sBh, uint32_t* sBl) {
    int kp = tid >> 4, dv4 = (tid & 15) << 2;
    int k0 = kp * 2;
    int kc = k0 >> 4, lk = k0 & 15;
    int t = (lk >> 1) & 3, reg = (lk >> 3) & 1;
    const float* e = (const float*)&fb[0];   // even-k row values
    const float* o = (const float*)&fb[1];   // odd-k row values
    #pragma unroll
    for (int j = 0; j < 4; j++) {
        int n = dv4 + j;
        int idx = ((kc * 4 + (n >> 4)) * 32 + (n & 7) * 4 + t) * 4
                + ((n >> 3) & 1) * 2 + reg;
        uint32_t hp, lp;
        split2(e[j], o[j], hp, lp);
        sBh[idx] = hp;
        sBl[idx] = lp;
    }
}

__device__ __forceinline__ void compute_chunk(const uint32_t* buf, int wm, int wn,
                                              int lane, float acc[2][4][4]) {
    const uint32_t* sAh = buf;
    const uint32_t* sAl = buf + 2048;
    const uint32_t* sBh = buf + 4096;
    const uint32_t* sBl = buf + 5120;
    #pragma unroll
    for (int kc = 0; kc < 2; kc++) {
        uint4 Ah[2], Al[2], Bh[2], Bl[2];
        #pragma unroll
        for (int mtl = 0; mtl < 2; mtl++) {
            int idx = ((kc * 8 + wm * 2 + mtl) * 32 + lane) * 4;
            Ah[mtl] = *(const uint4*)&sAh[idx];
            Al[mtl] = *(const uint4*)&sAl[idx];
        }
        #pragma unroll
        for (int p = 0; p < 2; p++) {
            int idx = ((kc * 4 + wn * 2 + p) * 32 + lane) * 4;
            Bh[p] = *(const uint4*)&sBh[idx];
            Bl[p] = *(const uint4*)&sBl[idx];
        }
        #pragma unroll
        for (int mtl = 0; mtl < 2; mtl++) {
            #pragma unroll
            for (int p = 0; p < 2; p++) {
                mma16(acc[mtl][p * 2],     Ah[mtl], Bh[p].x, Bh[p].y);
                mma16(acc[mtl][p * 2],     Ah[mtl], Bl[p].x, Bl[p].y);
                mma16(acc[mtl][p * 2],     Al[mtl], Bh[p].x, Bh[p].y);
                mma16(acc[mtl][p * 2 + 1], Ah[mtl], Bh[p].z, Bh[p].w);
                mma16(acc[mtl][p * 2 + 1], Ah[mtl], Bl[p].z, Bl[p].w);
                mma16(acc[mtl][p * 2 + 1], Al[mtl], Bh[p].z, Bh[p].w);
            }
        }
    }
}

template<bool BTRANS>
__device__ __forceinline__ void gemm_core(
    const float* __restrict__ Ab, size_t lda,
    const float* __restrict__ Bb, size_t ldb,
    float* __restrict__ Cb, size_t ldc,
    float scale, int nchunk, uint32_t* sm)
{
    int tid = threadIdx.x, lane = tid & 31, wid = tid >> 5;
    int wm = wid & 3, wn = wid >> 2;
    int g = lane >> 2, t = lane & 3;
    uint32_t* buf0 = sm;
    uint32_t* buf1 = sm + 6144;

    float4 fa[4], fb[2];
    float acc[2][4][4] = {};

    // prologue: stage chunk 0
    loadA4(Ab, lda, tid, fa);
    if (!BTRANS) loadB2(Bb, ldb, tid, fb);
    else         loadBT(Bb, ldb, tid, fb);
    storeA4(fa, tid, buf0, buf0 + 2048);
    if (!BTRANS) storeB2(fb, tid, buf0 + 4096, buf0 + 5120);
    else         storeBT(fb, tid, buf0 + 4096, buf0 + 5120);
    __syncthreads();

    for (int c = 0; c < nchunk; c++) {
        uint32_t* cur = (c & 1) ? buf1 : buf0;
        uint32_t* nxt = (c & 1) ? buf0 : buf1;
        if (c + 1 < nchunk) {
            loadA4(Ab + (c + 1) * 32, lda, tid, fa);
            if (!BTRANS) loadB2(Bb + (c + 1) * 32, ldb, tid, fb);
            else         loadBT(Bb + (size_t)(c + 1) * 32 * ldb, ldb, tid, fb);
        }
        compute_chunk(cur, wm, wn, lane, acc);
        if (c + 1 < nchunk) {
            storeA4(fa, tid, nxt, nxt + 2048);
            if (!BTRANS) storeB2(fb, tid, nxt + 4096, nxt + 5120);
            else         storeBT(fb, tid, nxt + 4096, nxt + 5120);
        }
        __syncthreads();
    }

    // epilogue
    #pragma unroll
    for (int mtl = 0; mtl < 2; mtl++) {
        #pragma unroll
        for (int nt = 0; nt < 4; nt++) {
            size_t row = (size_t)(wm * 32 + mtl * 16 + g);
            size_t col = (size_t)(wn * 32 + nt * 8 + t * 2);
            float2 v0 = {acc[mtl][nt][0] * scale, acc[mtl][nt][1] * scale};
            float2 v1 = {acc[mtl][nt][2] * scale, acc[mtl][nt][3] * scale};
            *(float2*)&Cb[row * ldc + col] = v0;
            *(float2*)&Cb[(row + 8) * ldc + col] = v1;
        }
    }
}

// ---------------- kernels ----------------
__global__ __launch_bounds__(256) void proj_mma(const float* __restrict__ A,
                                                const float* __restrict__ W,
                                                float* __restrict__ C) {
    extern __shared__ uint32_t sm[];
    gemm_core<false>(A + (size_t)blockIdx.y * 128 * DM, DM,
                     W + (size_t)blockIdx.x * 64 * DM, DM,
                     C + (size_t)blockIdx.y * 128 * DM + blockIdx.x * 64, DM,
                     1.0f, DM / 32, sm);
}

__global__ __launch_bounds__(256) void scores_mma(const float* __restrict__ qp,
                                                  const float* __restrict__ kp,
                                                  float* __restrict__ attn) {
    extern __shared__ uint32_t sm[];
    int bh = blockIdx.z, b = bh >> 3, h = bh & 7;
    size_t sq0 = (size_t)blockIdx.y * 128, sk0 = (size_t)blockIdx.x * 64;
    gemm_core<false>(qp + ((size_t)b * S_ + sq0) * DM + h * 64, DM,
                     kp + ((size_t)b * S_ + sk0) * DM + h * 64, DM,
                     attn + ((size_t)bh * S_ + sq0) * S_ + sk0, S_,
                     0.125f, 2, sm);
}

__global__ __launch_bounds__(256) void av_mma(const float* __restrict__ attn,
                                              const float* __restrict__ vp,
                                              float* __restrict__ oh) {
    extern __shared__ uint32_t sm[];
    int bh = blockIdx.y, b = bh >> 3, h = bh & 7;
    size_t sq0 = (size_t)blockIdx.x * 128;
    gemm_core<true>(attn + ((size_t)bh * S_ + sq0) * S_, S_,
                    vp + (size_t)b * S_ * DM + h * 64, DM,
                    oh + ((size_t)b * S_ + sq0) * DM + h * 64, DM,
                    1.0f, S_ / 32, sm);
}

// ---------------- LayerNorm ----------------
__global__ void ln_kernel(const float* __restrict__ x, float* __restrict__ y,
                          const float* __restrict__ g, const float* __restrict__ bb) {
    int row = blockIdx.x;
    int tid = threadIdx.x;
    const float* xr = x + (size_t)row * DM;
    float v0 = xr[tid], v1 = xr[tid + 256];
    __shared__ float red[256];
    red[tid] = v0 + v1;
    __syncthreads();
    for (int o = 128; o > 0; o >>= 1) { if (tid < o) red[tid] += red[tid + o]; __syncthreads(); }
    float mu = red[0] * (1.0f / DM);
    __syncthreads();
    float d0 = v0 - mu, d1 = v1 - mu;
    red[tid] = d0 * d0 + d1 * d1;
    __syncthreads();
    for (int o = 128; o > 0; o >>= 1) { if (tid < o) red[tid] += red[tid + o]; __syncthreads(); }
    float rstd = rsqrtf(red[0] * (1.0f / DM) + 1e-5f);
    float* yr = y + (size_t)row * DM;
    yr[tid]       = d0 * rstd * g[tid]       + bb[tid];
    yr[tid + 256] = d1 * rstd * g[tid + 256] + bb[tid + 256];
}

// ---------------- softmax in place over rows of 2048 (float4) ----------------
__global__ __launch_bounds__(256) void softmax_kernel(float* __restrict__ attn) {
    size_t row = blockIdx.x;
    float4* p = (float4*)(attn + row * (size_t)S_);
    int tid = threadIdx.x;
    float4 v0 = p[tid], v1 = p[tid + 256];
    float m = fmaxf(fmaxf(fmaxf(v0.x, v0.y), fmaxf(v0.z, v0.w)),
                    fmaxf(fmaxf(v1.x, v1.y), fmaxf(v1.z, v1.w)));
    __shared__ float red[256];
    red[tid] = m;
    __syncthreads();
    for (int o = 128; o > 0; o >>= 1) { if (tid < o) red[tid] = fmaxf(red[tid], red[tid + o]); __syncthreads(); }
    m = red[0];
    __syncthreads();
    v0.x = __expf(v0.x - m); v0.y = __expf(v0.y - m); v0.z = __expf(v0.z - m); v0.w = __expf(v0.w - m);
    v1.x = __expf(v1.x - m); v1.y = __expf(v1.y - m); v1.z = __expf(v1.z - m); v1.w = __expf(v1.w - m);
    float s = v0.x + v0.y + v0.z + v0.w + v1.x + v1.y + v1.z + v1.w;
    red[tid] = s;
    __syncthreads();
    for (int o = 128; o > 0; o >>= 1) { if (tid < o) red[tid] += red[tid + o]; __syncthreads(); }
    float inv = 1.0f / red[0];
    v0.x *= inv; v0.y *= inv; v0.z *= inv; v0.w *= inv;
    v1.x *= inv; v1.y *= inv; v1.z *= inv; v1.w *= inv;
    p[tid] = v0;
    p[tid + 256] = v1;
}

extern "C" void kernel_launch(void* const* d_in, const int* in_sizes, int n_in,
                              void* d_out, int out_size) {
    const float* q    = (const float*)d_in[0];
    const float* k    = (const float*)d_in[1];
    const float* v    = (const float*)d_in[2];
    const float* W_Q  = (const float*)d_in[3];
    const float* W_K  = (const float*)d_in[4];
    const float* W_V  = (const float*)d_in[5];
    const float* W_fc = (const float*)d_in[6];
    const float* ln_g = (const float*)d_in[7];
    const float* ln_b = (const float*)d_in[8];

    float* out  = (float*)d_out;                       // [B,S,512]
    float* attn = out + (size_t)B_ * S_ * DM;          // [B,H,S,S]

    float *buf, *qp, *kp, *vp, *oh;
    cudaGetSymbolAddress((void**)&buf, g_buf);
    cudaGetSymbolAddress((void**)&qp,  g_qp);
    cudaGetSymbolAddress((void**)&kp,  g_kp);
    cudaGetSymbolAddress((void**)&vp,  g_vp);
    cudaGetSymbolAddress((void**)&oh,  g_oh);

    const int SMEM = 48 * 1024;
    cudaFuncSetAttribute(proj_mma,   cudaFuncAttributeMaxDynamicSharedMemorySize, SMEM);
    cudaFuncSetAttribute(scores_mma, cudaFuncAttributeMaxDynamicSharedMemorySize, SMEM);
    cudaFuncSetAttribute(av_mma,     cudaFuncAttributeMaxDynamicSharedMemorySize, SMEM);

    const int ROWS = B_ * S_;                          // 8192
    dim3 proj_grid(DM / 64, ROWS / 128);               // (8, 64)

    // Q path
    ln_kernel<<<ROWS, 256>>>(q, buf, ln_g, ln_b);
    proj_mma<<<proj_grid, 256, SMEM>>>(buf, W_Q, qp);
    // K path
    ln_kernel<<<ROWS, 256>>>(k, buf, ln_g, ln_b);
    proj_mma<<<proj_grid, 256, SMEM>>>(buf, W_K, kp);
    // V path
    ln_kernel<<<ROWS, 256>>>(v, buf, ln_g, ln_b);
    proj_mma<<<proj_grid, 256, SMEM>>>(buf, W_V, vp);

    // Attention
    scores_mma<<<dim3(S_ / 64, S_ / 128, B_ * H_), 256, SMEM>>>(qp, kp, attn);
    softmax_kernel<<<B_ * H_ * S_, 256>>>(attn);
    av_mma<<<dim3(S_ / 128, B_ * H_), 256, SMEM>>>(attn, vp, oh);

    // Output LN + fc
    ln_kernel<<<ROWS, 256>>>(oh, buf, ln_g, ln_b);
    proj_mma<<<proj_grid, 256, SMEM>>>(buf, W_fc, out);
}